// round 14
// baseline (speedup 1.0000x reference)
#include <cuda_runtime.h>
#include <cstdint>

// Quantized SiLU (per-row scales), S=8192 rows, H=4096 cols.
//   x_f   = x * scale_x[row]
//   y_q   = clip(rint(sigmoid(x_f) / scale_y[row]), -127, 127)
//   y_f   = y_q * scale_y[row]
//   out_q = clip(rint((x_f * y_f) / scale_out[row]), -127, 127)
//
// x is int8-valued => only 255 distinct inputs per row; per-CTA shared-mem
// LUT turns each element into index+LDS work.
//
// R14 = R13 (cp.async staging: 26 regs, occ 90%, main 37.9us) + progressive
// group drain. Thread t's staged data is written by thread t's own cp.async,
// so only the LUT needs the barrier; the 4 chunks are 4 commit groups and
// are processed as they land (wait_group 3/2/1/0) instead of blocking the
// whole CTA on the full row.
//
// x arrives promoted to a 4-byte type (int32 or float32); values always in
// [-127,127], so the index decodes per element branch-free.
// Output: float32 [S*H out_q values][S scale_out values].

#define LOG2E 1.44269504088896340736f

// word -> LUT index in [0,254]
__device__ __forceinline__ int decode_idx(int w) {
    float fi = (float)w;                              // int32 interpretation
    int   wf = __float2int_rn(__int_as_float(w));     // float32 interpretation
    return ((fabsf(fi) > 127.5f) ? wf : w) + 127;
}

__device__ __forceinline__ float lut_entry(int i, float scale_x, float scale_y,
                                           float scale_o) {
    float f   = (float)(i - 127);
    float xf  = f * scale_x;
    float e   = exp2f(-xf * LOG2E);                   // exp(-x_f)
    float sig = __frcp_rn(1.0f + e);                  // sigmoid(x_f)
    float yq  = fminf(rintf(sig / scale_y), 127.0f);  // sigmoid>0: upper clip only
    float oq  = rintf(xf * (yq * scale_y) / scale_o);
    return fminf(fmaxf(oq, -127.0f), 127.0f);
}

__global__ void __launch_bounds__(256) silu_cpasync_kernel(
    const int4* __restrict__ x,
    const float* __restrict__ scale_x_v,
    const float* __restrict__ scale_y_v,
    const float* __restrict__ scale_out_v,
    float4* __restrict__ out,
    float* __restrict__ tail_dst,
    int write_tail)
{
    __shared__ float lut[256];
    __shared__ int4  stage[1024];      // full 16KB row
    int row = blockIdx.x;
    int t = threadIdx.x;

    long base = (long)row * 1024 + t;  // int4 index

    // Stage the row global->shared: 4 chunks, 4 separate commit groups, so
    // they can be drained progressively. No payload registers.
    {
        unsigned sa = (unsigned)__cvta_generic_to_shared(&stage[t]);
        const int4* g = x + base;
        #pragma unroll
        for (int k = 0; k < 4; k++) {
            asm volatile(
                "cp.async.cg.shared.global [%0], [%1], 16;"
                :: "r"(sa + k * 4096u), "l"(g + k * 256)
                : "memory");
            asm volatile("cp.async.commit_group;" ::: "memory");
        }
    }

    float scale_x = __ldg(&scale_x_v[row]);
    float scale_y = __ldg(&scale_y_v[row]);
    float scale_o = __ldg(&scale_out_v[row]);

    // LUT build + barrier overlap the async copies (no dependency on them:
    // each thread reads only its OWN staged chunks afterwards).
    if (t < 255)
        lut[t] = lut_entry(t, scale_x, scale_y, scale_o);
    if (write_tail && t == 0) tail_dst[row] = scale_o;
    __syncthreads();   // LUT visibility only

    // Progressive drain: process chunk k as soon as its group has landed,
    // while later chunks are still in flight.
    asm volatile("cp.async.wait_group 3;" ::: "memory");
    {
        int4 v = stage[t];
        float4 r;
        r.x = lut[decode_idx(v.x)]; r.y = lut[decode_idx(v.y)];
        r.z = lut[decode_idx(v.z)]; r.w = lut[decode_idx(v.w)];
        __stcs(out + base, r);
    }
    asm volatile("cp.async.wait_group 2;" ::: "memory");
    {
        int4 v = stage[t + 256];
        float4 r;
        r.x = lut[decode_idx(v.x)]; r.y = lut[decode_idx(v.y)];
        r.z = lut[decode_idx(v.z)]; r.w = lut[decode_idx(v.w)];
        __stcs(out + base + 256, r);
    }
    asm volatile("cp.async.wait_group 1;" ::: "memory");
    {
        int4 v = stage[t + 512];
        float4 r;
        r.x = lut[decode_idx(v.x)]; r.y = lut[decode_idx(v.y)];
        r.z = lut[decode_idx(v.z)]; r.w = lut[decode_idx(v.w)];
        __stcs(out + base + 512, r);
    }
    asm volatile("cp.async.wait_group 0;" ::: "memory");
    {
        int4 v = stage[t + 768];
        float4 r;
        r.x = lut[decode_idx(v.x)]; r.y = lut[decode_idx(v.y)];
        r.z = lut[decode_idx(v.z)]; r.w = lut[decode_idx(v.w)];
        __stcs(out + base + 768, r);
    }
}

// Generic fallback for unexpected shapes (direct evaluation).
__device__ __forceinline__ float decode_elem(int w) {
    float fi = (float)w;
    float ff = __int_as_float(w);
    return (fabsf(fi) > 127.5f) ? ff : fi;
}

__global__ void __launch_bounds__(256) silu_quant_generic_kernel(
    const int* __restrict__ x,
    const float* __restrict__ scale_x_v,
    const float* __restrict__ scale_y_v,
    const float* __restrict__ scale_out_v,
    float* __restrict__ out,
    int H, long total)
{
    long i = (long)blockIdx.x * blockDim.x + threadIdx.x;
    if (i >= total) return;
    int row = (int)(i / H);
    float scale_x = scale_x_v[row];
    float scale_y = scale_y_v[row];
    float f   = decode_elem(x[i]);
    float xf  = f * scale_x;
    float e   = exp2f(-xf * LOG2E);
    float sig = __frcp_rn(1.0f + e);
    float yq  = fminf(rintf(sig / scale_y), 127.0f);
    float oq  = rintf(xf * (yq * scale_y) / scale_out_v[row]);
    out[i] = fminf(fmaxf(oq, -127.0f), 127.0f);
}

__global__ void tail_pad_kernel(const float* __restrict__ scale_o,
                                float* __restrict__ dst, int S, long extra) {
    long i = (long)blockIdx.x * blockDim.x + threadIdx.x;
    if (i >= extra) return;
    dst[i] = (i < S) ? scale_o[i] : 0.0f;
}

extern "C" void kernel_launch(void* const* d_in, const int* in_sizes, int n_in,
                              void* d_out, int out_size) {
    const void* x         = d_in[0];
    const float* scale_x  = (const float*)d_in[1];
    const float* scale_y  = (const float*)d_in[2];
    const float* scale_o  = (const float*)d_in[3];

    int S = in_sizes[1];            // rows (scale_x element count)
    int H = in_sizes[0] / S;        // cols
    long total = (long)S * H;
    long extra = (long)out_size - total;
    float* out = (float*)d_out;

    if (H == 4096) {
        int write_tail = (extra >= (long)S) ? 1 : 0;
        silu_cpasync_kernel<<<S, 256>>>(
            (const int4*)x, scale_x, scale_y, scale_o,
            (float4*)out, out + total, write_tail);
        if (extra > (long)S) {
            long pad = extra - S;
            tail_pad_kernel<<<(int)((pad + 255) / 256), 256>>>(
                scale_o + S, out + total + S, 0, pad);
        } else if (extra > 0 && !write_tail) {
            tail_pad_kernel<<<(int)((extra + 255) / 256), 256>>>(
                scale_o, out + total, (int)extra, extra);
        }
    } else {
        long blocks = (total + 255) / 256;
        silu_quant_generic_kernel<<<(unsigned)blocks, 256>>>(
            (const int*)x, scale_x, scale_y, scale_o, out, H, total);
        if (extra > 0) {
            tail_pad_kernel<<<(int)((extra + 255) / 256), 256>>>(
                scale_o, out + total, (int)(extra < S ? extra : S), extra);
        }
    }
}

// round 15
// speedup vs baseline: 1.0057x; 1.0057x over previous
#include <cuda_runtime.h>
#include <cstdint>

// Quantized SiLU (per-row scales), S=8192 rows, H=4096 cols.
//   x_f   = x * scale_x[row]
//   y_q   = clip(rint(sigmoid(x_f) / scale_y[row]), -127, 127)
//   y_f   = y_q * scale_y[row]
//   out_q = clip(rint((x_f * y_f) / scale_out[row]), -127, 127)
//
// x is int8-valued => only 255 distinct inputs per row; per-CTA shared-mem
// LUT turns each element into index+LDS work.
//
// R15 = R14 (cp.async staging, 24 regs, occ 90.7%, progressive 4-group
// drain — best measured main kernel, 37.2us) with ALL streaming cache
// hints removed: across R7..R14, every total measured with __ldcs/__stcs
// was >= 44.4us while the only hint-free round hit 43.5us at equal
// ncu-main; .cs evict-first stores appear to cost DRAM write efficiency
// in the steady-state timed loop. Plain LDG/STG everywhere.
//
// x arrives promoted to a 4-byte type (int32 or float32); values always in
// [-127,127], so the index decodes per element branch-free.
// Output: float32 [S*H out_q values][S scale_out values].

#define LOG2E 1.44269504088896340736f

// word -> LUT index in [0,254]
__device__ __forceinline__ int decode_idx(int w) {
    float fi = (float)w;                              // int32 interpretation
    int   wf = __float2int_rn(__int_as_float(w));     // float32 interpretation
    return ((fabsf(fi) > 127.5f) ? wf : w) + 127;
}

__device__ __forceinline__ float lut_entry(int i, float scale_x, float scale_y,
                                           float scale_o) {
    float f   = (float)(i - 127);
    float xf  = f * scale_x;
    float e   = exp2f(-xf * LOG2E);                   // exp(-x_f)
    float sig = __frcp_rn(1.0f + e);                  // sigmoid(x_f)
    float yq  = fminf(rintf(sig / scale_y), 127.0f);  // sigmoid>0: upper clip only
    float oq  = rintf(xf * (yq * scale_y) / scale_o);
    return fminf(fmaxf(oq, -127.0f), 127.0f);
}

__global__ void __launch_bounds__(256) silu_cpasync_kernel(
    const int4* __restrict__ x,
    const float* __restrict__ scale_x_v,
    const float* __restrict__ scale_y_v,
    const float* __restrict__ scale_out_v,
    float4* __restrict__ out,
    float* __restrict__ tail_dst,
    int write_tail)
{
    __shared__ float lut[256];
    __shared__ int4  stage[1024];      // full 16KB row
    int row = blockIdx.x;
    int t = threadIdx.x;

    long base = (long)row * 1024 + t;  // int4 index

    // Stage the row global->shared: 4 chunks, 4 separate commit groups, so
    // they can be drained progressively. No payload registers.
    {
        unsigned sa = (unsigned)__cvta_generic_to_shared(&stage[t]);
        const int4* g = x + base;
        #pragma unroll
        for (int k = 0; k < 4; k++) {
            asm volatile(
                "cp.async.cg.shared.global [%0], [%1], 16;"
                :: "r"(sa + k * 4096u), "l"(g + k * 256)
                : "memory");
            asm volatile("cp.async.commit_group;" ::: "memory");
        }
    }

    float scale_x = __ldg(&scale_x_v[row]);
    float scale_y = __ldg(&scale_y_v[row]);
    float scale_o = __ldg(&scale_out_v[row]);

    // LUT build + barrier overlap the async copies (no dependency on them:
    // each thread reads only its OWN staged chunks afterwards).
    if (t < 255)
        lut[t] = lut_entry(t, scale_x, scale_y, scale_o);
    if (write_tail && t == 0) tail_dst[row] = scale_o;
    __syncthreads();   // LUT visibility only

    // Progressive drain: process chunk k as soon as its group has landed,
    // while later chunks are still in flight. Plain stores (no .cs).
    asm volatile("cp.async.wait_group 3;" ::: "memory");
    {
        int4 v = stage[t];
        float4 r;
        r.x = lut[decode_idx(v.x)]; r.y = lut[decode_idx(v.y)];
        r.z = lut[decode_idx(v.z)]; r.w = lut[decode_idx(v.w)];
        out[base] = r;
    }
    asm volatile("cp.async.wait_group 2;" ::: "memory");
    {
        int4 v = stage[t + 256];
        float4 r;
        r.x = lut[decode_idx(v.x)]; r.y = lut[decode_idx(v.y)];
        r.z = lut[decode_idx(v.z)]; r.w = lut[decode_idx(v.w)];
        out[base + 256] = r;
    }
    asm volatile("cp.async.wait_group 1;" ::: "memory");
    {
        int4 v = stage[t + 512];
        float4 r;
        r.x = lut[decode_idx(v.x)]; r.y = lut[decode_idx(v.y)];
        r.z = lut[decode_idx(v.z)]; r.w = lut[decode_idx(v.w)];
        out[base + 512] = r;
    }
    asm volatile("cp.async.wait_group 0;" ::: "memory");
    {
        int4 v = stage[t + 768];
        float4 r;
        r.x = lut[decode_idx(v.x)]; r.y = lut[decode_idx(v.y)];
        r.z = lut[decode_idx(v.z)]; r.w = lut[decode_idx(v.w)];
        out[base + 768] = r;
    }
}

// Generic fallback for unexpected shapes (direct evaluation).
__device__ __forceinline__ float decode_elem(int w) {
    float fi = (float)w;
    float ff = __int_as_float(w);
    return (fabsf(fi) > 127.5f) ? ff : fi;
}

__global__ void __launch_bounds__(256) silu_quant_generic_kernel(
    const int* __restrict__ x,
    const float* __restrict__ scale_x_v,
    const float* __restrict__ scale_y_v,
    const float* __restrict__ scale_out_v,
    float* __restrict__ out,
    int H, long total)
{
    long i = (long)blockIdx.x * blockDim.x + threadIdx.x;
    if (i >= total) return;
    int row = (int)(i / H);
    float scale_x = scale_x_v[row];
    float scale_y = scale_y_v[row];
    float f   = decode_elem(x[i]);
    float xf  = f * scale_x;
    float e   = exp2f(-xf * LOG2E);
    float sig = __frcp_rn(1.0f + e);
    float yq  = fminf(rintf(sig / scale_y), 127.0f);
    float oq  = rintf(xf * (yq * scale_y) / scale_out_v[row]);
    out[i] = fminf(fmaxf(oq, -127.0f), 127.0f);
}

__global__ void tail_pad_kernel(const float* __restrict__ scale_o,
                                float* __restrict__ dst, int S, long extra) {
    long i = (long)blockIdx.x * blockDim.x + threadIdx.x;
    if (i >= extra) return;
    dst[i] = (i < S) ? scale_o[i] : 0.0f;
}

extern "C" void kernel_launch(void* const* d_in, const int* in_sizes, int n_in,
                              void* d_out, int out_size) {
    const void* x         = d_in[0];
    const float* scale_x  = (const float*)d_in[1];
    const float* scale_y  = (const float*)d_in[2];
    const float* scale_o  = (const float*)d_in[3];

    int S = in_sizes[1];            // rows (scale_x element count)
    int H = in_sizes[0] / S;        // cols
    long total = (long)S * H;
    long extra = (long)out_size - total;
    float* out = (float*)d_out;

    if (H == 4096) {
        int write_tail = (extra >= (long)S) ? 1 : 0;
        silu_cpasync_kernel<<<S, 256>>>(
            (const int4*)x, scale_x, scale_y, scale_o,
            (float4*)out, out + total, write_tail);
        if (extra > (long)S) {
            long pad = extra - S;
            tail_pad_kernel<<<(int)((pad + 255) / 256), 256>>>(
                scale_o + S, out + total + S, 0, pad);
        } else if (extra > 0 && !write_tail) {
            tail_pad_kernel<<<(int)((extra + 255) / 256), 256>>>(
                scale_o, out + total, (int)extra, extra);
        }
    } else {
        long blocks = (total + 255) / 256;
        silu_quant_generic_kernel<<<(unsigned)blocks, 256>>>(
            (const int*)x, scale_x, scale_y, scale_o, out, H, total);
        if (extra > 0) {
            tail_pad_kernel<<<(int)((extra + 255) / 256), 256>>>(
                scale_o, out + total, (int)(extra < S ? extra : S), extra);
        }
    }
}